// round 6
// baseline (speedup 1.0000x reference)
#include <cuda_runtime.h>

// SeathruNeRF RGB renderer: fused, 4 samples per lane, float4 memory ops.
// One warp per ray (R=16384), S=256 = 2 chunks of 128; lane l owns samples
// c*128+4l .. +3. Quad-sum + 5-step warp scan over quad totals + registered
// in-quad prefixes -> 42 SHFL per 128 samples. All LDG/STG are 128-bit.

#define FULL 0xffffffffu
#define S_SAMPLES 256

__device__ __forceinline__ float clip01(float x) {
    return fminf(fmaxf(x, 0.0f), 1.0f);
}

__global__ __launch_bounds__(256, 2)
void seathru_kernel(const float* __restrict__ orgb,
                    const float* __restrict__ mrgb,
                    const float* __restrict__ dc,
                    const float* __restrict__ bsc,
                    const float* __restrict__ dens,
                    const float* __restrict__ delt,
                    float* __restrict__ out,
                    int R)
{
    const int gwarp = (blockIdx.x * blockDim.x + threadIdx.x) >> 5;
    if (gwarp >= R) return;
    const int lane = threadIdx.x & 31;
    const int r = gwarp;

    const int base1 = r * S_SAMPLES;        // scalar arrays (floats)
    const int base3 = r * S_SAMPLES * 3;    // vec3 arrays (floats)

    const long long RS = (long long)R * S_SAMPLES;
    float* outT = out + 12LL * R + (long long)r * S_SAMPLES;
    float* outA = outT + RS;
    float* outW = outA + RS;

    float carry[7];
    #pragma unroll
    for (int k = 0; k < 7; k++) carry[k] = 0.f;

    float a_rx = 0.f, a_ry = 0.f, a_rz = 0.f;
    float a_dx = 0.f, a_dy = 0.f, a_dz = 0.f;
    float a_bx = 0.f, a_by = 0.f, a_bz = 0.f;
    float a_m  = 0.f;

    #pragma unroll
    for (int c = 0; c < 2; c++) {
        // ---- batch 1 of loads: scan inputs + orgb (11 x LDG.128) ----
        const float4* dl4 = (const float4*)(delt + base1 + c * 128);
        const float4* dn4 = (const float4*)(dens + base1 + c * 128);
        const float4* c4  = (const float4*)(dc   + base3 + c * 384);
        const float4* b4  = (const float4*)(bsc  + base3 + c * 384);
        const float4* o4  = (const float4*)(orgb + base3 + c * 384);

        const float4 dv = __ldcs(&dl4[lane]);
        const float4 rv = __ldcs(&dn4[lane]);
        const float4 cA = __ldcs(&c4[3 * lane + 0]);
        const float4 cB = __ldcs(&c4[3 * lane + 1]);
        const float4 cC = __ldcs(&c4[3 * lane + 2]);
        const float4 bA = __ldcs(&b4[3 * lane + 0]);
        const float4 bB = __ldcs(&b4[3 * lane + 1]);
        const float4 bC = __ldcs(&b4[3 * lane + 2]);
        const float4 oA = __ldcs(&o4[3 * lane + 0]);
        const float4 oB = __ldcs(&o4[3 * lane + 1]);
        const float4 oC = __ldcs(&o4[3 * lane + 2]);

        if (c == 0 && lane == 0) {
            float* o_dc0 = out + 12LL * R + 3LL * RS;
            float* o_bs0 = out + 15LL * R + 3LL * RS;
            o_dc0[3 * r + 0] = cA.x;
            o_dc0[3 * r + 1] = cA.y;
            o_dc0[3 * r + 2] = cA.z;
            o_bs0[3 * r + 0] = bA.x;
            o_bs0[3 * r + 1] = bA.y;
            o_bs0[3 * r + 2] = bA.z;
        }

        const float d0 = dv.x, d1 = dv.y, d2 = dv.z, d3 = dv.w;
        float dd[4];
        dd[0] = d0 * rv.x; dd[1] = d1 * rv.y; dd[2] = d2 * rv.z; dd[3] = d3 * rv.w;

        // unpack vec3 per sample from the three float4 slices
        // sample j components: [12l+3j, +1, +2]
        float dcv0[3] = {cA.x, cA.y, cA.z};
        float dcv1[3] = {cA.w, cB.x, cB.y};
        float dcv2[3] = {cB.z, cB.w, cC.x};
        float dcv3[3] = {cC.y, cC.z, cC.w};
        float bd[4][3];
        bd[0][0] = bA.x * d0; bd[0][1] = bA.y * d0; bd[0][2] = bA.z * d0;
        bd[1][0] = bA.w * d1; bd[1][1] = bB.x * d1; bd[1][2] = bB.y * d1;
        bd[2][0] = bB.z * d2; bd[2][1] = bB.w * d2; bd[2][2] = bC.x * d2;
        bd[3][0] = bC.y * d3; bd[3][1] = bC.z * d3; bd[3][2] = bC.w * d3;

        // per-field in-quad running prefixes and quad totals
        // field 0: dd; fields 1..3: dd + dc_k*d; fields 4..6: dd + bd_k
        float r1[7], r2[7], r3[7], q[7];
        {
            // field 0
            r1[0] = dd[0];
            r2[0] = r1[0] + dd[1];
            r3[0] = r2[0] + dd[2];
            q[0]  = r3[0] + dd[3];
            #pragma unroll
            for (int k = 0; k < 3; k++) {
                const float f0 = dd[0] + dcv0[k] * d0;
                const float f1 = dd[1] + dcv1[k] * d1;
                const float f2 = dd[2] + dcv2[k] * d2;
                const float f3 = dd[3] + dcv3[k] * d3;
                r1[1 + k] = f0;
                r2[1 + k] = f0 + f1;
                r3[1 + k] = r2[1 + k] + f2;
                q[1 + k]  = r3[1 + k] + f3;
            }
            #pragma unroll
            for (int k = 0; k < 3; k++) {
                const float f0 = dd[0] + bd[0][k];
                const float f1 = dd[1] + bd[1][k];
                const float f2 = dd[2] + bd[2][k];
                const float f3 = dd[3] + bd[3][k];
                r1[4 + k] = f0;
                r2[4 + k] = f0 + f1;
                r3[4 + k] = r2[4 + k] + f2;
                q[4 + k]  = r3[4 + k] + f3;
            }
        }

        // 5-step Kogge-Stone scan over quad totals, 7 fields interleaved
        float inc[7];
        #pragma unroll
        for (int k = 0; k < 7; k++) inc[k] = q[k];
        #pragma unroll
        for (int off = 1; off < 32; off <<= 1) {
            float n[7];
            #pragma unroll
            for (int k = 0; k < 7; k++) n[k] = __shfl_up_sync(FULL, inc[k], off);
            if (lane >= off) {
                #pragma unroll
                for (int k = 0; k < 7; k++) inc[k] += n[k];
            }
        }

        // exclusive base at this lane's sample 0
        float eb[7];
        #pragma unroll
        for (int k = 0; k < 7; k++) {
            eb[k] = carry[k] + inc[k] - q[k];
            carry[k] += __shfl_sync(FULL, inc[k], 31);
        }

        // ---- batch 2 of loads: mrgb (3 x LDG.128), in flight during exps ----
        const float4* m4 = (const float4*)(mrgb + base3 + c * 384);
        const float4 mA = __ldcs(&m4[3 * lane + 0]);
        const float4 mB = __ldcs(&m4[3 * lane + 1]);
        const float4 mC = __ldcs(&m4[3 * lane + 2]);

        // T / alpha / weight per sample; float4 stores
        float T[4], alpha[4], w[4];
        T[0] = __expf(-eb[0]);
        T[1] = __expf(-(eb[0] + r1[0]));
        T[2] = __expf(-(eb[0] + r2[0]));
        T[3] = __expf(-(eb[0] + r3[0]));
        #pragma unroll
        for (int j = 0; j < 4; j++) {
            alpha[j] = 1.0f - __expf(-dd[j]);
            w[j] = T[j] * alpha[j];
        }
        {
            float4* t4 = (float4*)(outT + c * 128);
            float4* a4 = (float4*)(outA + c * 128);
            float4* w4 = (float4*)(outW + c * 128);
            __stcs(&t4[lane], make_float4(T[0], T[1], T[2], T[3]));
            __stcs(&a4[lane], make_float4(alpha[0], alpha[1], alpha[2], alpha[3]));
            __stcs(&w4[lane], make_float4(w[0], w[1], w[2], w[3]));
        }

        const float ox[4] = {oA.x, oA.w, oB.z, oC.y};
        const float oy[4] = {oA.y, oB.x, oB.w, oC.z};
        const float oz[4] = {oA.z, oB.y, oC.x, oC.w};

        #pragma unroll
        for (int j = 0; j < 4; j++) {
            a_m  += w[j];
            a_rx += w[j] * ox[j];
            a_ry += w[j] * oy[j];
            a_rz += w[j] * oz[j];
        }

        // direct: exp(-(eb[1+k] + prefix_j)) * alpha_j * o_k
        #pragma unroll
        for (int j = 0; j < 4; j++) {
            const float p1 = (j == 0) ? 0.f : (j == 1) ? r1[1] : (j == 2) ? r2[1] : r3[1];
            const float p2 = (j == 0) ? 0.f : (j == 1) ? r1[2] : (j == 2) ? r2[2] : r3[2];
            const float p3 = (j == 0) ? 0.f : (j == 1) ? r1[3] : (j == 2) ? r2[3] : r3[3];
            a_dx += __expf(-(eb[1] + p1)) * alpha[j] * ox[j];
            a_dy += __expf(-(eb[2] + p2)) * alpha[j] * oy[j];
            a_dz += __expf(-(eb[3] + p3)) * alpha[j] * oz[j];
        }

        const float mx[4] = {mA.x, mA.w, mB.z, mC.y};
        const float my[4] = {mA.y, mB.x, mB.w, mC.z};
        const float mz[4] = {mA.z, mB.y, mC.x, mC.w};

        // backscatter: exp(-(eb[4+k] + prefix_j)) * (1 - exp(-bd_jk)) * m_k
        #pragma unroll
        for (int j = 0; j < 4; j++) {
            const float p4 = (j == 0) ? 0.f : (j == 1) ? r1[4] : (j == 2) ? r2[4] : r3[4];
            const float p5 = (j == 0) ? 0.f : (j == 1) ? r1[5] : (j == 2) ? r2[5] : r3[5];
            const float p6 = (j == 0) ? 0.f : (j == 1) ? r1[6] : (j == 2) ? r2[6] : r3[6];
            a_bx += __expf(-(eb[4] + p4)) * (1.0f - __expf(-bd[j][0])) * mx[j];
            a_by += __expf(-(eb[5] + p5)) * (1.0f - __expf(-bd[j][1])) * my[j];
            a_bz += __expf(-(eb[6] + p6)) * (1.0f - __expf(-bd[j][2])) * mz[j];
        }
    }

    // warp butterfly reduce of the 10 accumulators
    #pragma unroll
    for (int off = 16; off >= 1; off >>= 1) {
        a_rx += __shfl_xor_sync(FULL, a_rx, off);
        a_ry += __shfl_xor_sync(FULL, a_ry, off);
        a_rz += __shfl_xor_sync(FULL, a_rz, off);
        a_dx += __shfl_xor_sync(FULL, a_dx, off);
        a_dy += __shfl_xor_sync(FULL, a_dy, off);
        a_dz += __shfl_xor_sync(FULL, a_dz, off);
        a_bx += __shfl_xor_sync(FULL, a_bx, off);
        a_by += __shfl_xor_sync(FULL, a_by, off);
        a_bz += __shfl_xor_sync(FULL, a_bz, off);
        a_m  += __shfl_xor_sync(FULL, a_m,  off);
    }

    if (lane == 0) {
        float* o_rgb  = out + 0LL;
        float* o_rest = out + 3LL * R;
        float* o_dir  = out + 6LL * R;
        float* o_bs   = out + 9LL * R;
        float* o_mask = out + 18LL * R + 3LL * RS;

        o_rgb[3 * r + 0] = clip01(a_dx + a_bx);
        o_rgb[3 * r + 1] = clip01(a_dy + a_by);
        o_rgb[3 * r + 2] = clip01(a_dz + a_bz);

        o_rest[3 * r + 0] = clip01(a_rx);
        o_rest[3 * r + 1] = clip01(a_ry);
        o_rest[3 * r + 2] = clip01(a_rz);

        o_dir[3 * r + 0] = clip01(a_dx);
        o_dir[3 * r + 1] = clip01(a_dy);
        o_dir[3 * r + 2] = clip01(a_dz);

        o_bs[3 * r + 0] = clip01(a_bx);
        o_bs[3 * r + 1] = clip01(a_by);
        o_bs[3 * r + 2] = clip01(a_bz);

        o_mask[r] = clip01(a_m);
    }
}

extern "C" void kernel_launch(void* const* d_in, const int* in_sizes, int n_in,
                              void* d_out, int out_size) {
    const float* orgb = (const float*)d_in[0];
    const float* mrgb = (const float*)d_in[1];
    const float* dc   = (const float*)d_in[2];
    const float* bsc  = (const float*)d_in[3];
    const float* dens = (const float*)d_in[4];
    const float* delt = (const float*)d_in[5];
    float* out = (float*)d_out;

    const int R = in_sizes[4] / S_SAMPLES;   // densities is R*S elements

    const int threads = 256;               // 8 warps = 8 rays per block
    const int blocks = (R * 32 + threads - 1) / threads;
    seathru_kernel<<<blocks, threads>>>(orgb, mrgb, dc, bsc, dens, delt, out, R);
}

// round 7
// speedup vs baseline: 1.0075x; 1.0075x over previous
#include <cuda_runtime.h>

// SeathruNeRF RGB renderer: fused, 4 samples per lane, float4 memory ops,
// PHASE-SPLIT scan to cap registers at 84 (3 blocks x 256 thr = 24 warps/SM).
// Phase A: fields 0-3 (object density + direct), retire dc/orgb regs.
// Phase B: fields 4-6 (backscatter), retire bsc/mrgb regs.

#define FULL 0xffffffffu
#define S_SAMPLES 256

__device__ __forceinline__ float clip01(float x) {
    return fminf(fmaxf(x, 0.0f), 1.0f);
}

__global__ __launch_bounds__(256, 3)
void seathru_kernel(const float* __restrict__ orgb,
                    const float* __restrict__ mrgb,
                    const float* __restrict__ dc,
                    const float* __restrict__ bsc,
                    const float* __restrict__ dens,
                    const float* __restrict__ delt,
                    float* __restrict__ out,
                    int R)
{
    const int gwarp = (blockIdx.x * blockDim.x + threadIdx.x) >> 5;
    if (gwarp >= R) return;
    const int lane = threadIdx.x & 31;
    const int r = gwarp;

    const int base1 = r * S_SAMPLES;
    const int base3 = r * S_SAMPLES * 3;

    const long long RS = (long long)R * S_SAMPLES;
    float* outT = out + 12LL * R + (long long)r * S_SAMPLES;
    float* outA = outT + RS;
    float* outW = outA + RS;

    float carry[7];
    #pragma unroll
    for (int k = 0; k < 7; k++) carry[k] = 0.f;

    float a_rx = 0.f, a_ry = 0.f, a_rz = 0.f;
    float a_dx = 0.f, a_dy = 0.f, a_dz = 0.f;
    float a_bx = 0.f, a_by = 0.f, a_bz = 0.f;
    float a_m  = 0.f;

    #pragma unroll
    for (int c = 0; c < 2; c++) {
        // ---- loads: scan-critical first, then payloads ----
        const float4* dl4 = (const float4*)(delt + base1 + c * 128);
        const float4* dn4 = (const float4*)(dens + base1 + c * 128);
        const float4* c4  = (const float4*)(dc   + base3 + c * 384);
        const float4* b4  = (const float4*)(bsc  + base3 + c * 384);
        const float4* o4  = (const float4*)(orgb + base3 + c * 384);

        const float4 dv = __ldcs(&dl4[lane]);
        const float4 rv = __ldcs(&dn4[lane]);
        const float4 cA = __ldcs(&c4[3 * lane + 0]);
        const float4 cB = __ldcs(&c4[3 * lane + 1]);
        const float4 cC = __ldcs(&c4[3 * lane + 2]);
        const float4 bA = __ldcs(&b4[3 * lane + 0]);
        const float4 bB = __ldcs(&b4[3 * lane + 1]);
        const float4 bC = __ldcs(&b4[3 * lane + 2]);
        const float4 oA = __ldcs(&o4[3 * lane + 0]);
        const float4 oB = __ldcs(&o4[3 * lane + 1]);
        const float4 oC = __ldcs(&o4[3 * lane + 2]);

        if (c == 0 && lane == 0) {
            float* o_dc0 = out + 12LL * R + 3LL * RS;
            float* o_bs0 = out + 15LL * R + 3LL * RS;
            o_dc0[3 * r + 0] = cA.x;
            o_dc0[3 * r + 1] = cA.y;
            o_dc0[3 * r + 2] = cA.z;
            o_bs0[3 * r + 0] = bA.x;
            o_bs0[3 * r + 1] = bA.y;
            o_bs0[3 * r + 2] = bA.z;
        }

        float dd[4];
        dd[0] = dv.x * rv.x; dd[1] = dv.y * rv.y;
        dd[2] = dv.z * rv.z; dd[3] = dv.w * rv.w;

        // ============ PHASE A: fields 0..3 (object + direct) ============
        float r1[4], r2[4], r3[4], q[4];
        {
            r1[0] = dd[0];
            r2[0] = r1[0] + dd[1];
            r3[0] = r2[0] + dd[2];
            q[0]  = r3[0] + dd[3];

            // direct fields: dd_j + dc_jk * d_j  (dc unpack from cA,cB,cC)
            const float dcu[4][3] = {
                {cA.x, cA.y, cA.z}, {cA.w, cB.x, cB.y},
                {cB.z, cB.w, cC.x}, {cC.y, cC.z, cC.w}};
            const float dl[4] = {dv.x, dv.y, dv.z, dv.w};
            #pragma unroll
            for (int k = 0; k < 3; k++) {
                const float f0 = dd[0] + dcu[0][k] * dl[0];
                const float f1 = dd[1] + dcu[1][k] * dl[1];
                const float f2 = dd[2] + dcu[2][k] * dl[2];
                const float f3 = dd[3] + dcu[3][k] * dl[3];
                r1[1 + k] = f0;
                r2[1 + k] = f0 + f1;
                r3[1 + k] = r2[1 + k] + f2;
                q[1 + k]  = r3[1 + k] + f3;
            }
        }

        float inc[4];
        #pragma unroll
        for (int k = 0; k < 4; k++) inc[k] = q[k];
        #pragma unroll
        for (int off = 1; off < 32; off <<= 1) {
            float n[4];
            #pragma unroll
            for (int k = 0; k < 4; k++) n[k] = __shfl_up_sync(FULL, inc[k], off);
            if (lane >= off) {
                #pragma unroll
                for (int k = 0; k < 4; k++) inc[k] += n[k];
            }
        }

        float eb[4];
        #pragma unroll
        for (int k = 0; k < 4; k++) {
            eb[k] = carry[k] + inc[k] - q[k];
            carry[k] += __shfl_sync(FULL, inc[k], 31);
        }

        // mrgb loads issue here: latency hidden under phase-A exps + phase-B scan
        const float4* m4 = (const float4*)(mrgb + base3 + c * 384);
        const float4 mA = __ldcs(&m4[3 * lane + 0]);
        const float4 mB = __ldcs(&m4[3 * lane + 1]);
        const float4 mC = __ldcs(&m4[3 * lane + 2]);

        float T[4], alpha[4], w[4];
        T[0] = __expf(-eb[0]);
        T[1] = __expf(-(eb[0] + r1[0]));
        T[2] = __expf(-(eb[0] + r2[0]));
        T[3] = __expf(-(eb[0] + r3[0]));
        #pragma unroll
        for (int j = 0; j < 4; j++) {
            alpha[j] = 1.0f - __expf(-dd[j]);
            w[j] = T[j] * alpha[j];
        }
        {
            float4* t4 = (float4*)(outT + c * 128);
            float4* a4 = (float4*)(outA + c * 128);
            float4* w4 = (float4*)(outW + c * 128);
            __stcs(&t4[lane], make_float4(T[0], T[1], T[2], T[3]));
            __stcs(&a4[lane], make_float4(alpha[0], alpha[1], alpha[2], alpha[3]));
            __stcs(&w4[lane], make_float4(w[0], w[1], w[2], w[3]));
        }

        {
            const float ox[4] = {oA.x, oA.w, oB.z, oC.y};
            const float oy[4] = {oA.y, oB.x, oB.w, oC.z};
            const float oz[4] = {oA.z, oB.y, oC.x, oC.w};

            #pragma unroll
            for (int j = 0; j < 4; j++) {
                a_m  += w[j];
                a_rx += w[j] * ox[j];
                a_ry += w[j] * oy[j];
                a_rz += w[j] * oz[j];
            }
            #pragma unroll
            for (int j = 0; j < 4; j++) {
                const float p1 = (j == 0) ? 0.f : (j == 1) ? r1[1] : (j == 2) ? r2[1] : r3[1];
                const float p2 = (j == 0) ? 0.f : (j == 1) ? r1[2] : (j == 2) ? r2[2] : r3[2];
                const float p3 = (j == 0) ? 0.f : (j == 1) ? r1[3] : (j == 2) ? r2[3] : r3[3];
                a_dx += __expf(-(eb[1] + p1)) * alpha[j] * ox[j];
                a_dy += __expf(-(eb[2] + p2)) * alpha[j] * oy[j];
                a_dz += __expf(-(eb[3] + p3)) * alpha[j] * oz[j];
            }
        }
        // dc/orgb/eb/T/w registers all dead here

        // ============ PHASE B: fields 4..6 (backscatter) ============
        float bd[4][3];
        {
            const float dl[4] = {dv.x, dv.y, dv.z, dv.w};
            bd[0][0] = bA.x * dl[0]; bd[0][1] = bA.y * dl[0]; bd[0][2] = bA.z * dl[0];
            bd[1][0] = bA.w * dl[1]; bd[1][1] = bB.x * dl[1]; bd[1][2] = bB.y * dl[1];
            bd[2][0] = bB.z * dl[2]; bd[2][1] = bB.w * dl[2]; bd[2][2] = bC.x * dl[2];
            bd[3][0] = bC.y * dl[3]; bd[3][1] = bC.z * dl[3]; bd[3][2] = bC.w * dl[3];
        }

        float s1[3], s2[3], s3[3], qb[3];
        #pragma unroll
        for (int k = 0; k < 3; k++) {
            const float f0 = dd[0] + bd[0][k];
            const float f1 = dd[1] + bd[1][k];
            const float f2 = dd[2] + bd[2][k];
            const float f3 = dd[3] + bd[3][k];
            s1[k] = f0;
            s2[k] = f0 + f1;
            s3[k] = s2[k] + f2;
            qb[k] = s3[k] + f3;
        }

        float incb[3];
        #pragma unroll
        for (int k = 0; k < 3; k++) incb[k] = qb[k];
        #pragma unroll
        for (int off = 1; off < 32; off <<= 1) {
            float n[3];
            #pragma unroll
            for (int k = 0; k < 3; k++) n[k] = __shfl_up_sync(FULL, incb[k], off);
            if (lane >= off) {
                #pragma unroll
                for (int k = 0; k < 3; k++) incb[k] += n[k];
            }
        }

        float ebb[3];
        #pragma unroll
        for (int k = 0; k < 3; k++) {
            ebb[k] = carry[4 + k] + incb[k] - qb[k];
            carry[4 + k] += __shfl_sync(FULL, incb[k], 31);
        }

        {
            const float mx[4] = {mA.x, mA.w, mB.z, mC.y};
            const float my[4] = {mA.y, mB.x, mB.w, mC.z};
            const float mz[4] = {mA.z, mB.y, mC.x, mC.w};

            #pragma unroll
            for (int j = 0; j < 4; j++) {
                const float p4 = (j == 0) ? 0.f : (j == 1) ? s1[0] : (j == 2) ? s2[0] : s3[0];
                const float p5 = (j == 0) ? 0.f : (j == 1) ? s1[1] : (j == 2) ? s2[1] : s3[1];
                const float p6 = (j == 0) ? 0.f : (j == 1) ? s1[2] : (j == 2) ? s2[2] : s3[2];
                a_bx += __expf(-(ebb[0] + p4)) * (1.0f - __expf(-bd[j][0])) * mx[j];
                a_by += __expf(-(ebb[1] + p5)) * (1.0f - __expf(-bd[j][1])) * my[j];
                a_bz += __expf(-(ebb[2] + p6)) * (1.0f - __expf(-bd[j][2])) * mz[j];
            }
        }
    }

    // warp butterfly reduce of the 10 accumulators
    #pragma unroll
    for (int off = 16; off >= 1; off >>= 1) {
        a_rx += __shfl_xor_sync(FULL, a_rx, off);
        a_ry += __shfl_xor_sync(FULL, a_ry, off);
        a_rz += __shfl_xor_sync(FULL, a_rz, off);
        a_dx += __shfl_xor_sync(FULL, a_dx, off);
        a_dy += __shfl_xor_sync(FULL, a_dy, off);
        a_dz += __shfl_xor_sync(FULL, a_dz, off);
        a_bx += __shfl_xor_sync(FULL, a_bx, off);
        a_by += __shfl_xor_sync(FULL, a_by, off);
        a_bz += __shfl_xor_sync(FULL, a_bz, off);
        a_m  += __shfl_xor_sync(FULL, a_m,  off);
    }

    if (lane == 0) {
        float* o_rgb  = out + 0LL;
        float* o_rest = out + 3LL * R;
        float* o_dir  = out + 6LL * R;
        float* o_bs   = out + 9LL * R;
        float* o_mask = out + 18LL * R + 3LL * RS;

        o_rgb[3 * r + 0] = clip01(a_dx + a_bx);
        o_rgb[3 * r + 1] = clip01(a_dy + a_by);
        o_rgb[3 * r + 2] = clip01(a_dz + a_bz);

        o_rest[3 * r + 0] = clip01(a_rx);
        o_rest[3 * r + 1] = clip01(a_ry);
        o_rest[3 * r + 2] = clip01(a_rz);

        o_dir[3 * r + 0] = clip01(a_dx);
        o_dir[3 * r + 1] = clip01(a_dy);
        o_dir[3 * r + 2] = clip01(a_dz);

        o_bs[3 * r + 0] = clip01(a_bx);
        o_bs[3 * r + 1] = clip01(a_by);
        o_bs[3 * r + 2] = clip01(a_bz);

        o_mask[r] = clip01(a_m);
    }
}

extern "C" void kernel_launch(void* const* d_in, const int* in_sizes, int n_in,
                              void* d_out, int out_size) {
    const float* orgb = (const float*)d_in[0];
    const float* mrgb = (const float*)d_in[1];
    const float* dc   = (const float*)d_in[2];
    const float* bsc  = (const float*)d_in[3];
    const float* dens = (const float*)d_in[4];
    const float* delt = (const float*)d_in[5];
    float* out = (float*)d_out;

    const int R = in_sizes[4] / S_SAMPLES;   // densities is R*S elements

    const int threads = 256;               // 8 warps = 8 rays per block
    const int blocks = (R * 32 + threads - 1) / threads;
    seathru_kernel<<<blocks, threads>>>(orgb, mrgb, dc, bsc, dens, delt, out, R);
}